// round 5
// baseline (speedup 1.0000x reference)
#include <cuda_runtime.h>
#include <cuda_fp16.h>
#include <cstdint>
#include <cstddef>

#define BSZ   8192
#define DIMN  100
#define NSTEP 49
#define WH    256
#define RRATE 0.05f

// ---------------- device scratch (static, no allocations) ----------------
__device__ float g_volpre[(size_t)NSTEP * BSZ * DIMN]; // 160.6 MB
__device__ float g_Sbuf[2][BSZ * DIMN];
__device__ float g_hdual[2][(size_t)2 * BSZ * WH];     // dual-MLP activations [16384][256]
__device__ float g_grad[BSZ * DIMN];
__device__ float g_vbuf[2][BSZ];
__device__ float g_stoch[BSZ];
__device__ float g_err[BSZ];
// transposed weights: Wt[n*K + k] = W[k*N + n]
__device__ float g_Wgt_in[WH * DIMN];
__device__ float g_Wgt_h[3][WH * WH];
__device__ float g_Wgt_out[DIMN * WH];
__device__ float g_Wvt_in[WH * DIMN];
__device__ float g_Wvt_h[3][WH * WH];

// ---------------- helpers ----------------
__device__ __forceinline__ void split2(float x0, float x1, uint32_t& h, uint32_t& l) {
    __half2 hh = __floats2half2_rn(x0, x1);
    float2 hf = __half22float2(hh);
    __half2 ll = __floats2half2_rn(x0 - hf.x, x1 - hf.y);
    h = *reinterpret_cast<uint32_t*>(&hh);
    l = *reinterpret_cast<uint32_t*>(&ll);
}
__device__ __forceinline__ void mma16(float d[4], const uint32_t a[4], const uint32_t b[2]) {
    asm volatile(
        "mma.sync.aligned.m16n8k16.row.col.f32.f16.f16.f32 "
        "{%0,%1,%2,%3}, {%4,%5,%6,%7}, {%8,%9}, {%0,%1,%2,%3};"
        : "+f"(d[0]), "+f"(d[1]), "+f"(d[2]), "+f"(d[3])
        : "r"(a[0]), "r"(a[1]), "r"(a[2]), "r"(a[3]), "r"(b[0]), "r"(b[1]));
}

// smem geometry: [row][kpair] words, row stride SP=12 (conflict-free fragment loads)
#define SP       12
#define A_WORDS  (128 * SP)                 // Ah/Al: 128 rows
#define B_WORDS  (64 * SP)                  // Bh/Bl: 64 rows
#define BUF_W    (2 * A_WORDS + 2 * B_WORDS)
#define DYN_SMEM (2 * BUF_W * 4)            // 36864 bytes

// ================= mma.sync fp16 (3x-split) GEMM, dual-weight =================
// C[M,N] = act( A @ Wt^T + bias + t*w0 );  CTA tile 128x64, BK=16, 256 thr, 2 CTA/SM
// blocks with blockIdx.y >= halfBlocks use the *1 weight set (dual-MLP M-stacking).
// wrapA: A row index taken mod BSZ (dual layer-1 reads the same input for both halves).
__global__ __launch_bounds__(256, 2)
void gemm_mma(const float* __restrict__ A,
              const float* __restrict__ Wt0, const float* __restrict__ Wt1,
              const float* __restrict__ bias0, const float* __restrict__ bias1,
              const float* __restrict__ w00, const float* __restrict__ w01,
              const float* __restrict__ tg, int tIdx,
              float* __restrict__ C, int N, int K, int relu,
              int halfBlocks, int wrapA)
{
    extern __shared__ uint32_t smw[];

    const int tid    = threadIdx.x;
    const int lane   = tid & 31;
    const int wid    = tid >> 5;
    const int warp_m = wid & 3;        // 4 warps down M  -> 32 rows each
    const int warp_n = wid >> 2;       // 2 warps along N -> 32 cols each
    const int mBase  = blockIdx.y * 128;
    const int nBase  = blockIdx.x * 64;
    const bool hiH   = (int)blockIdx.y >= halfBlocks;
    const float* Wt   = hiH ? Wt1   : Wt0;
    const float* bias = hiH ? bias1 : bias0;
    const float* w0   = hiH ? w01   : w00;

    const int qrow = lane >> 2;        // 0..7
    const int qk   = lane & 3;         // 0..3

    float acc[2][4][4];
#pragma unroll
    for (int i = 0; i < 2; ++i)
#pragma unroll
        for (int j = 0; j < 4; ++j)
#pragma unroll
            for (int q = 0; q < 4; ++q) acc[i][j][q] = 0.f;

    // global-load indices
    const int r0  = tid >> 2;                  // 0..63
    const int r1  = r0 + 64;
    const int c40 = (tid & 3) << 2;            // k offset 0,4,8,12
    const int kp0 = (tid & 3) << 1;            // kpair word 0,2,4,6
    int ar0 = mBase + r0, ar1 = mBase + r1;
    if (wrapA) { ar0 &= (BSZ - 1); ar1 &= (BSZ - 1); }
    const int gn = nBase + r0;                 // B row (output col)

    const int nChunks = (K + 15) >> 4;

    float4 av0, av1, bv0;
    auto prefetch = [&](int kc) {
        const int gc = (kc << 4) + c40;
        av0 = av1 = bv0 = make_float4(0.f, 0.f, 0.f, 0.f);
        if (gc < K) {
            av0 = *(const float4*)(A + (size_t)ar0 * K + gc);
            av1 = *(const float4*)(A + (size_t)ar1 * K + gc);
            if (gn < N) bv0 = *(const float4*)(Wt + (size_t)gn * K + gc);
        }
    };
    auto store = [&](int b) {
        uint32_t* Ah = smw + b * BUF_W;
        uint32_t* Al = Ah + A_WORDS;
        uint32_t* Bh = Ah + 2 * A_WORDS;
        uint32_t* Bl = Bh + B_WORDS;
        uint32_t h0, l0, h1, l1;
        split2(av0.x, av0.y, h0, l0); split2(av0.z, av0.w, h1, l1);
        Ah[r0 * SP + kp0] = h0; Ah[r0 * SP + kp0 + 1] = h1;
        Al[r0 * SP + kp0] = l0; Al[r0 * SP + kp0 + 1] = l1;
        split2(av1.x, av1.y, h0, l0); split2(av1.z, av1.w, h1, l1);
        Ah[r1 * SP + kp0] = h0; Ah[r1 * SP + kp0 + 1] = h1;
        Al[r1 * SP + kp0] = l0; Al[r1 * SP + kp0 + 1] = l1;
        split2(bv0.x, bv0.y, h0, l0); split2(bv0.z, bv0.w, h1, l1);
        Bh[r0 * SP + kp0] = h0; Bh[r0 * SP + kp0 + 1] = h1;
        Bl[r0 * SP + kp0] = l0; Bl[r0 * SP + kp0 + 1] = l1;
    };

    prefetch(0);
    store(0);

    for (int kc = 0; kc < nChunks; ++kc) {
        __syncthreads();                       // single barrier per chunk
        const bool more = (kc + 1 < nChunks);
        if (more) prefetch(kc + 1);

        const uint32_t* Ah = smw + (kc & 1) * BUF_W;
        const uint32_t* Al = Ah + A_WORDS;
        const uint32_t* Bh = Ah + 2 * A_WORDS;
        const uint32_t* Bl = Bh + B_WORDS;

        uint32_t ah[2][4], xl[2][4], bh[4][2], bl[4][2];
#pragma unroll
        for (int im = 0; im < 2; ++im) {
            int m0 = warp_m * 32 + im * 16 + qrow;
            ah[im][0] = Ah[m0 * SP + qk];
            ah[im][1] = Ah[(m0 + 8) * SP + qk];
            ah[im][2] = Ah[m0 * SP + qk + 4];
            ah[im][3] = Ah[(m0 + 8) * SP + qk + 4];
        }
#pragma unroll
        for (int jn = 0; jn < 4; ++jn) {
            int n0 = warp_n * 32 + jn * 8 + qrow;
            bh[jn][0] = Bh[n0 * SP + qk];
            bh[jn][1] = Bh[n0 * SP + qk + 4];
        }
#pragma unroll
        for (int im = 0; im < 2; ++im)
#pragma unroll
            for (int jn = 0; jn < 4; ++jn) mma16(acc[im][jn], ah[im], bh[jn]);

#pragma unroll
        for (int jn = 0; jn < 4; ++jn) {
            int n0 = warp_n * 32 + jn * 8 + qrow;
            bl[jn][0] = Bl[n0 * SP + qk];
            bl[jn][1] = Bl[n0 * SP + qk + 4];
        }
#pragma unroll
        for (int im = 0; im < 2; ++im)
#pragma unroll
            for (int jn = 0; jn < 4; ++jn) mma16(acc[im][jn], ah[im], bl[jn]);

#pragma unroll
        for (int im = 0; im < 2; ++im) {
            int m0 = warp_m * 32 + im * 16 + qrow;
            xl[im][0] = Al[m0 * SP + qk];
            xl[im][1] = Al[(m0 + 8) * SP + qk];
            xl[im][2] = Al[m0 * SP + qk + 4];
            xl[im][3] = Al[(m0 + 8) * SP + qk + 4];
        }
#pragma unroll
        for (int im = 0; im < 2; ++im)
#pragma unroll
            for (int jn = 0; jn < 4; ++jn) mma16(acc[im][jn], xl[im], bh[jn]);

        if (more) store((kc + 1) & 1);
    }

    // ---------------- epilogue ----------------
    const float tval = w0 ? __ldg(tg + tIdx) : 0.f;
#pragma unroll
    for (int jn = 0; jn < 4; ++jn) {
        int c = nBase + warp_n * 32 + jn * 8 + 2 * qk;
        if (c >= N) continue;
        float b0 = 0.f, b1 = 0.f;
        if (bias) { b0 = __ldg(bias + c); b1 = __ldg(bias + c + 1); }
        if (w0)   { b0 += tval * __ldg(w0 + c); b1 += tval * __ldg(w0 + c + 1); }
#pragma unroll
        for (int im = 0; im < 2; ++im) {
            int r = mBase + warp_m * 32 + im * 16 + qrow;
            float o00 = acc[im][jn][0] + b0, o01 = acc[im][jn][1] + b1;
            float o10 = acc[im][jn][2] + b0, o11 = acc[im][jn][3] + b1;
            if (relu) {
                o00 = fmaxf(o00, 0.f); o01 = fmaxf(o01, 0.f);
                o10 = fmaxf(o10, 0.f); o11 = fmaxf(o11, 0.f);
            }
            *(float2*)(C + (size_t)r * N + c)       = make_float2(o00, o01);
            *(float2*)(C + (size_t)(r + 8) * N + c) = make_float2(o10, o11);
        }
    }
}

// ---------------- fused weight transposes (ONE launch) ----------------
#define WT_TOTAL (25600 + 25600 + 196608 + 196608 + 25600)
__global__ void wtrans_all(const float* __restrict__ Wg_in, const float* __restrict__ Wv_in,
                           const float* __restrict__ Wg_h,  const float* __restrict__ Wv_h,
                           const float* __restrict__ Wg_out,
                           float* __restrict__ Wgt_in, float* __restrict__ Wvt_in,
                           float* __restrict__ Wgt_h,  float* __restrict__ Wvt_h,
                           float* __restrict__ Wgt_out)
{
    for (int i = blockIdx.x * blockDim.x + threadIdx.x; i < WT_TOTAL;
         i += gridDim.x * blockDim.x) {
        int j = i;
        if (j < 25600) {                       // Wg_in (101x256, skip row 0) -> [256][100]
            int n = j / 100, k = j % 100;
            Wgt_in[j] = Wg_in[(size_t)(k + 1) * WH + n];
        } else if ((j -= 25600) < 25600) {     // Wv_in
            int n = j / 100, k = j % 100;
            Wvt_in[j] = Wv_in[(size_t)(k + 1) * WH + n];
        } else if ((j -= 25600) < 196608) {    // Wg_h (3 x 256x256)
            int l = j / 65536, r = j % 65536;
            int n = r / 256, k = r % 256;
            Wgt_h[j] = Wg_h[(size_t)l * 65536 + (size_t)k * WH + n];
        } else if ((j -= 196608) < 196608) {   // Wv_h
            int l = j / 65536, r = j % 65536;
            int n = r / 256, k = r % 256;
            Wvt_h[j] = Wv_h[(size_t)l * 65536 + (size_t)k * WH + n];
        } else {                                // Wg_out (256x100) -> [100][256]
            j -= 196608;
            int n = j / 256, k = j % 256;
            Wgt_out[j] = Wg_out[(size_t)k * DIMN + n];
        }
    }
}

// ---------------- GEMV: out[b] = H[b,:]·w + b0 ----------
__global__ __launch_bounds__(256) void gemv_kernel(
    const float* __restrict__ H, const float* __restrict__ w,
    const float* __restrict__ b, float* __restrict__ out)
{
    __shared__ __align__(16) float ws[WH];
    ws[threadIdx.x] = w[threadIdx.x];
    __syncthreads();
    int warp = threadIdx.x >> 5, lane = threadIdx.x & 31;
    int row = blockIdx.x * 8 + warp;
    const float4* hr = (const float4*)(H + (size_t)row * WH);
    const float4* wr = (const float4*)ws;
    float acc = 0.f;
#pragma unroll
    for (int q = 0; q < 2; ++q) {
        float4 h4 = hr[q * 32 + lane];
        float4 w4 = wr[q * 32 + lane];
        acc += h4.x * w4.x + h4.y * w4.y + h4.z * w4.z + h4.w * w4.w;
    }
#pragma unroll
    for (int o = 16; o; o >>= 1) acc += __shfl_xor_sync(0xffffffffu, acc, o);
    if (lane == 0) out[row] = acc + b[0];
}

// ---------------- step: vol, stoch_int, S update ----------------
__global__ __launch_bounds__(256) void step_kernel(
    const float* __restrict__ S_old, const float* __restrict__ vp,
    const float* __restrict__ grad, const float* __restrict__ tg, int i,
    float* __restrict__ S_new, float* __restrict__ stoch)
{
    int warp = threadIdx.x >> 5, lane = threadIdx.x & 31;
    int b = blockIdx.x * 8 + warp;
    float h  = tg[i + 1] - tg[i];
    float sq = sqrtf(h);
    float rh = RRATE * h;
    const float* Sr = S_old + (size_t)b * DIMN;
    const float* vr = vp   + (size_t)b * DIMN;
    const float* gr = grad + (size_t)b * DIMN;
    float acc = 0.f;
    for (int d = lane; d < DIMN; d += 32) {
        float s   = Sr[d];
        float vol = s * (vr[d] * sq);
        acc += gr[d] * vol;
        S_new[(size_t)b * DIMN + d] = s + rh * s + vol;
    }
#pragma unroll
    for (int o = 16; o; o >>= 1) acc += __shfl_xor_sync(0xffffffffu, acc, o);
    if (lane == 0) stoch[b] = acc;
}

// ---------------- error accumulation ----------------
__global__ void err_kernel(const float* __restrict__ vNew, const float* __restrict__ vOld,
                           const float* __restrict__ stoch, const float* __restrict__ tg,
                           int i, float* __restrict__ err)
{
    int b = blockIdx.x * blockDim.x + threadIdx.x;
    if (b >= BSZ) return;
    float h = tg[i + 1] - tg[i];
    float e = vNew[b] - vOld[b] * (1.f + RRATE * h) - stoch[b];
    err[b] += e * e;
}

// ---------------- output packing: [v_f | S_f | error] ----------------
__global__ void pack_kernel(const float* __restrict__ v, const float* __restrict__ S,
                            const float* __restrict__ err, float* __restrict__ out)
{
    int i = blockIdx.x * 256 + threadIdx.x;
    if (i < BSZ * DIMN) out[BSZ + i] = S[i];
    if (i < BSZ) {
        out[i] = v[i];
        out[BSZ + BSZ * DIMN + i] = err[i];
    }
}

// ---------------- host-side helpers ----------------
static void gemm(const float* A, const float* Wt, const float* bias, const float* w0,
                 const float* tg, int tIdx, float* C, int M, int N, int K, int relu)
{
    dim3 grid((N + 63) / 64, M / 128);
    gemm_mma<<<grid, 256, DYN_SMEM>>>(A, Wt, Wt, bias, bias, w0, w0, tg, tIdx,
                                      C, N, K, relu, 1 << 30, 0);
}

struct DualW {
    const float *Wgt_in, *Wvt_in, *Wgt_h, *Wvt_h;
    const float *bg_in, *bv_in, *bg_h, *bv_h;
    const float *Wg_in, *Wv_in;   // originals (row 0 = t weights)
};

// dual trunk: both MLPs (g rows 0..8191, v rows 8192..16383); result in hB
static void dual_trunk(const float* S, const float* tg, int tIdx, const DualW& W,
                       float* hA, float* hB)
{
    dim3 grid(WH / 64, 128);   // (4, 128) = 512 CTAs
    gemm_mma<<<grid, 256, DYN_SMEM>>>(S, W.Wgt_in, W.Wvt_in, W.bg_in, W.bv_in,
                                      W.Wg_in, W.Wv_in, tg, tIdx,
                                      hA, WH, DIMN, 1, 64, 1);
    gemm_mma<<<grid, 256, DYN_SMEM>>>(hA, W.Wgt_h, W.Wvt_h, W.bg_h, W.bv_h,
                                      nullptr, nullptr, nullptr, 0,
                                      hB, WH, WH, 1, 64, 0);
    gemm_mma<<<grid, 256, DYN_SMEM>>>(hB, W.Wgt_h + 65536, W.Wvt_h + 65536,
                                      W.bg_h + WH, W.bv_h + WH,
                                      nullptr, nullptr, nullptr, 0,
                                      hA, WH, WH, 1, 64, 0);
    gemm_mma<<<grid, 256, DYN_SMEM>>>(hA, W.Wgt_h + 2 * 65536, W.Wvt_h + 2 * 65536,
                                      W.bg_h + 2 * WH, W.bv_h + 2 * WH,
                                      nullptr, nullptr, nullptr, 0,
                                      hB, WH, WH, 1, 64, 0);
}

extern "C" void kernel_launch(void* const* d_in, const int* in_sizes, int n_in,
                              void* d_out, int out_size)
{
    const float* S0     = (const float*)d_in[0];
    const float* dW     = (const float*)d_in[1];
    const float* tg     = (const float*)d_in[2];
    const float* Vm     = (const float*)d_in[3];
    const float* Wg_in  = (const float*)d_in[4];
    const float* bg_in  = (const float*)d_in[5];
    const float* Wg_h   = (const float*)d_in[6];
    const float* bg_h   = (const float*)d_in[7];
    const float* Wg_out = (const float*)d_in[8];
    const float* bg_out = (const float*)d_in[9];
    const float* Wv_in  = (const float*)d_in[10];
    const float* bv_in  = (const float*)d_in[11];
    const float* Wv_h   = (const float*)d_in[12];
    const float* bv_h   = (const float*)d_in[13];
    const float* Wv_out = (const float*)d_in[14];
    const float* bv_out = (const float*)d_in[15];

    float *volpre, *Sb, *hd, *grad, *vb, *stoch, *err;
    float *Wgt_in, *Wgt_h, *Wgt_out, *Wvt_in, *Wvt_h;
    cudaGetSymbolAddress((void**)&volpre, g_volpre);
    cudaGetSymbolAddress((void**)&Sb,     g_Sbuf);
    cudaGetSymbolAddress((void**)&hd,     g_hdual);
    cudaGetSymbolAddress((void**)&grad,   g_grad);
    cudaGetSymbolAddress((void**)&vb,     g_vbuf);
    cudaGetSymbolAddress((void**)&stoch,  g_stoch);
    cudaGetSymbolAddress((void**)&err,    g_err);
    cudaGetSymbolAddress((void**)&Wgt_in, g_Wgt_in);
    cudaGetSymbolAddress((void**)&Wgt_h,  g_Wgt_h);
    cudaGetSymbolAddress((void**)&Wgt_out,g_Wgt_out);
    cudaGetSymbolAddress((void**)&Wvt_in, g_Wvt_in);
    cudaGetSymbolAddress((void**)&Wvt_h,  g_Wvt_h);

    float* Sbuf0 = Sb;
    float* Sbuf1 = Sb + (size_t)BSZ * DIMN;
    float* hA = hd;
    float* hB = hd + (size_t)2 * BSZ * WH;
    float* vA = vb;
    float* vBp = vb + BSZ;

    DualW W{Wgt_in, Wvt_in, Wgt_h, Wvt_h, bg_in, bv_in, bg_h, bv_h, Wg_in, Wv_in};

    // launch 0: weight transposes
    wtrans_all<<<512, 256>>>(Wg_in, Wv_in, Wg_h, Wv_h, Wg_out,
                             Wgt_in, Wvt_in, Wgt_h, Wvt_h, Wgt_out);

    // launch 1: volpre = dW @ V^T (B operand is V itself, [N,K] K-major)
    gemm(dW, Vm, nullptr, nullptr, nullptr, 0, volpre, NSTEP * BSZ, DIMN, DIMN, 0);

    // launches 2-5: dual trunk on [t0, S0]  (ncu -s 5 -c 1 lands on a dual hidden GEMM)
    dual_trunk(S0, tg, 0, W, hA, hB);
    gemm(hB, Wgt_out, bg_out, nullptr, nullptr, 0, grad, BSZ, DIMN, WH, 0); // grad_0
    gemv_kernel<<<BSZ / 8, 256>>>(hB + (size_t)BSZ * WH, Wv_out, bv_out, vA); // v_0

    cudaMemsetAsync(err, 0, BSZ * sizeof(float));

    const float* Scur = S0;
    float* vOld = vA;
    float* vNew = vBp;
    int sflip = 0;
    for (int i = 0; i < NSTEP; ++i) {
        float* Snew = sflip ? Sbuf1 : Sbuf0;
        // vol / stoch_int / S_new (uses grad_i = grad(t_i, S_i))
        step_kernel<<<BSZ / 8, 256>>>(Scur, volpre + (size_t)i * BSZ * DIMN,
                                      grad, tg, i, Snew, stoch);
        // both MLPs on [t_{i+1}, S_{i+1}] in one stacked trunk
        dual_trunk(Snew, tg, i + 1, W, hA, hB);
        gemm(hB, Wgt_out, bg_out, nullptr, nullptr, 0, grad, BSZ, DIMN, WH, 0); // grad_{i+1}
        gemv_kernel<<<BSZ / 8, 256>>>(hB + (size_t)BSZ * WH, Wv_out, bv_out, vNew); // v_{i+1}
        // error accumulation
        err_kernel<<<BSZ / 256, 256>>>(vNew, vOld, stoch, tg, i, err);

        Scur = Snew; sflip ^= 1;
        float* t = vOld; vOld = vNew; vNew = t;
    }

    // output: [v_f (8192) | S_f (8192*100) | error (8192)]
    pack_kernel<<<(BSZ * DIMN) / 256, 256>>>(vOld, Scur, err, (float*)d_out);
}

// round 6
// speedup vs baseline: 1.1043x; 1.1043x over previous
#include <cuda_runtime.h>
#include <cuda_fp16.h>
#include <cstdint>
#include <cstddef>

#define BSZ   8192
#define DIMN  100
#define NSTEP 49
#define WH    256
#define RRATE 0.05f

// ---------------- device scratch (static, no allocations) ----------------
__device__ float g_volpre[(size_t)NSTEP * BSZ * DIMN]; // 160.6 MB
__device__ float g_Sbuf[2][BSZ * DIMN];
__device__ float g_hdual[2][(size_t)2 * BSZ * WH];     // dual-MLP activations [16384][256]
__device__ float g_grad[BSZ * DIMN];
__device__ float g_vbuf[2][BSZ];
__device__ float g_stoch[BSZ];
__device__ float g_err[BSZ];
// transposed weights: Wt[n*K + k] = W[k*N + n]
__device__ float g_Wgt_in[WH * DIMN];
__device__ float g_Wgt_h[3][WH * WH];
__device__ float g_Wgt_out[DIMN * WH];
__device__ float g_Wvt_in[WH * DIMN];
__device__ float g_Wvt_h[3][WH * WH];

// ---------------- helpers ----------------
__device__ __forceinline__ uint32_t smem_u32(const void* p) {
    uint32_t a;
    asm("{ .reg .u64 t; cvta.to.shared.u64 t, %1; cvt.u32.u64 %0, t; }" : "=r"(a) : "l"(p));
    return a;
}
__device__ __forceinline__ void split2(float x0, float x1, uint32_t& h, uint32_t& l) {
    __half2 hh = __floats2half2_rn(x0, x1);
    float2 hf = __half22float2(hh);
    __half2 ll = __floats2half2_rn(x0 - hf.x, x1 - hf.y);
    h = *reinterpret_cast<uint32_t*>(&hh);
    l = *reinterpret_cast<uint32_t*>(&ll);
}
__device__ __forceinline__ void mma16(float d[4], const uint32_t a[4],
                                      uint32_t b0, uint32_t b1) {
    asm volatile(
        "mma.sync.aligned.m16n8k16.row.col.f32.f16.f16.f32 "
        "{%0,%1,%2,%3}, {%4,%5,%6,%7}, {%8,%9}, {%0,%1,%2,%3};"
        : "+f"(d[0]), "+f"(d[1]), "+f"(d[2]), "+f"(d[3])
        : "r"(a[0]), "r"(a[1]), "r"(a[2]), "r"(a[3]), "r"(b0), "r"(b1));
}
__device__ __forceinline__ void ldm4(uint32_t r[4], uint32_t addr) {
    asm volatile("ldmatrix.sync.aligned.m8n8.x4.shared.b16 {%0,%1,%2,%3}, [%4];"
                 : "=r"(r[0]), "=r"(r[1]), "=r"(r[2]), "=r"(r[3]) : "r"(addr));
}

// smem layout per buffer (bytes): rows of 16 halves, row stride 48B (stride-3 16B units)
//   Ah @ 0      (128 rows x 48B = 6144)
//   Al @ 6144
//   Bh @ 12288  (64 rows x 48B = 3072)
//   Bl @ 15360
#define BUF_BYTES 18432
#define DYN_SMEM  (2 * BUF_BYTES)        // 36864

// ================= mma.sync fp16 (3x-split) GEMM, dual-weight, ldmatrix ========
// C[M,N] = act( A @ Wt^T + bias + t*w0 );  CTA tile 128x64, BK=16, 256 thr, 2 CTA/SM
__global__ __launch_bounds__(256, 2)
void gemm_mma(const float* __restrict__ A,
              const float* __restrict__ Wt0, const float* __restrict__ Wt1,
              const float* __restrict__ bias0, const float* __restrict__ bias1,
              const float* __restrict__ w00, const float* __restrict__ w01,
              const float* __restrict__ tg, int tIdx,
              float* __restrict__ C, int N, int K, int relu,
              int halfBlocks, int wrapA)
{
    extern __shared__ uint32_t smw[];
    char* smc = (char*)smw;
    const uint32_t smemBase = smem_u32(smw);

    const int tid    = threadIdx.x;
    const int lane   = tid & 31;
    const int wid    = tid >> 5;
    const int warp_m = wid & 3;        // 4 warps down M  -> 32 rows each
    const int warp_n = wid >> 2;       // 2 warps along N -> 32 cols each
    const int mBase  = blockIdx.y * 128;
    const int nBase  = blockIdx.x * 64;
    const bool hiH   = (int)blockIdx.y >= halfBlocks;
    const float* Wt   = hiH ? Wt1   : Wt0;
    const float* bias = hiH ? bias1 : bias0;
    const float* w0   = hiH ? w01   : w00;

    const int qrow = lane >> 2;        // 0..7
    const int qk   = lane & 3;         // 0..3

    float acc[2][4][4];
#pragma unroll
    for (int i = 0; i < 2; ++i)
#pragma unroll
        for (int j = 0; j < 4; ++j)
#pragma unroll
            for (int q = 0; q < 4; ++q) acc[i][j][q] = 0.f;

    // global-load indices
    const int r0  = tid >> 2;                  // 0..63
    const int r1  = r0 + 64;
    const int c40 = (tid & 3) << 2;            // k offset 0,4,8,12
    int ar0 = mBase + r0, ar1 = mBase + r1;
    if (wrapA) { ar0 &= (BSZ - 1); ar1 &= (BSZ - 1); }
    const int gn = nBase + r0;                 // B row (output col)

    // ldmatrix source offsets (bytes, relative to buffer base)
    const int l15 = lane & 15;
    const int lc  = (lane >> 4) << 4;          // 0 or 16 (k-unit select)
    const uint32_t offA0 = (uint32_t)(warp_m * 32 + l15) * 48 + lc;
    const uint32_t offA1 = offA0 + 16 * 48;
    const uint32_t offB0 = 12288u + (uint32_t)(warp_n * 32 + l15) * 48 + lc;
    const uint32_t offB1 = offB0 + 16 * 48;

    const int nChunks = (K + 15) >> 4;

    float4 av0, av1, bv0;
    auto prefetch = [&](int kc) {
        const int gc = (kc << 4) + c40;
        av0 = av1 = bv0 = make_float4(0.f, 0.f, 0.f, 0.f);
        if (gc < K) {
            av0 = *(const float4*)(A + (size_t)ar0 * K + gc);
            av1 = *(const float4*)(A + (size_t)ar1 * K + gc);
            if (gn < N) bv0 = *(const float4*)(Wt + (size_t)gn * K + gc);
        }
    };
    auto store = [&](int b) {
        char* buf = smc + b * BUF_BYTES;
        const uint32_t rowOff0 = (uint32_t)r0 * 48 + c40 * 2;
        const uint32_t rowOff1 = (uint32_t)r1 * 48 + c40 * 2;
        uint32_t h0, l0, h1, l1;
        split2(av0.x, av0.y, h0, l0); split2(av0.z, av0.w, h1, l1);
        *(uint2*)(buf + rowOff0)        = make_uint2(h0, h1);
        *(uint2*)(buf + 6144 + rowOff0) = make_uint2(l0, l1);
        split2(av1.x, av1.y, h0, l0); split2(av1.z, av1.w, h1, l1);
        *(uint2*)(buf + rowOff1)        = make_uint2(h0, h1);
        *(uint2*)(buf + 6144 + rowOff1) = make_uint2(l0, l1);
        split2(bv0.x, bv0.y, h0, l0); split2(bv0.z, bv0.w, h1, l1);
        *(uint2*)(buf + 12288 + rowOff0) = make_uint2(h0, h1);
        *(uint2*)(buf + 15360 + rowOff0) = make_uint2(l0, l1);
    };

    prefetch(0);
    store(0);

    for (int kc = 0; kc < nChunks; ++kc) {
        __syncthreads();
        const bool more = (kc + 1 < nChunks);
        if (more) prefetch(kc + 1);

        const uint32_t base = smemBase + (kc & 1) * BUF_BYTES;

        uint32_t ah0[4], ah1[4], b0[4], b1[4];
        ldm4(ah0, base + offA0);
        ldm4(ah1, base + offA1);
        ldm4(b0,  base + offB0);
        ldm4(b1,  base + offB1);
        // pass 1: hi*hi     (b tile regs: [jn k0-7, jn+1 k0-7, jn k8-15, jn+1 k8-15])
        mma16(acc[0][0], ah0, b0[0], b0[2]);  mma16(acc[1][0], ah1, b0[0], b0[2]);
        mma16(acc[0][1], ah0, b0[1], b0[3]);  mma16(acc[1][1], ah1, b0[1], b0[3]);
        mma16(acc[0][2], ah0, b1[0], b1[2]);  mma16(acc[1][2], ah1, b1[0], b1[2]);
        mma16(acc[0][3], ah0, b1[1], b1[3]);  mma16(acc[1][3], ah1, b1[1], b1[3]);
        // pass 2: hi*lo
        ldm4(b0, base + offB0 + 3072);
        ldm4(b1, base + offB1 + 3072);
        mma16(acc[0][0], ah0, b0[0], b0[2]);  mma16(acc[1][0], ah1, b0[0], b0[2]);
        mma16(acc[0][1], ah0, b0[1], b0[3]);  mma16(acc[1][1], ah1, b0[1], b0[3]);
        mma16(acc[0][2], ah0, b1[0], b1[2]);  mma16(acc[1][2], ah1, b1[0], b1[2]);
        mma16(acc[0][3], ah0, b1[1], b1[3]);  mma16(acc[1][3], ah1, b1[1], b1[3]);
        // pass 3: lo*hi
        ldm4(ah0, base + offA0 + 6144);
        ldm4(ah1, base + offA1 + 6144);
        ldm4(b0,  base + offB0);
        ldm4(b1,  base + offB1);
        mma16(acc[0][0], ah0, b0[0], b0[2]);  mma16(acc[1][0], ah1, b0[0], b0[2]);
        mma16(acc[0][1], ah0, b0[1], b0[3]);  mma16(acc[1][1], ah1, b0[1], b0[3]);
        mma16(acc[0][2], ah0, b1[0], b1[2]);  mma16(acc[1][2], ah1, b1[0], b1[2]);
        mma16(acc[0][3], ah0, b1[1], b1[3]);  mma16(acc[1][3], ah1, b1[1], b1[3]);

        if (more) store((kc + 1) & 1);
    }

    // ---------------- epilogue ----------------
    const float tval = w0 ? __ldg(tg + tIdx) : 0.f;
#pragma unroll
    for (int jn = 0; jn < 4; ++jn) {
        int c = nBase + warp_n * 32 + jn * 8 + 2 * qk;
        if (c >= N) continue;
        float b0e = 0.f, b1e = 0.f;
        if (bias) { b0e = __ldg(bias + c); b1e = __ldg(bias + c + 1); }
        if (w0)   { b0e += tval * __ldg(w0 + c); b1e += tval * __ldg(w0 + c + 1); }
#pragma unroll
        for (int im = 0; im < 2; ++im) {
            int r = mBase + warp_m * 32 + im * 16 + qrow;
            float o00 = acc[im][jn][0] + b0e, o01 = acc[im][jn][1] + b1e;
            float o10 = acc[im][jn][2] + b0e, o11 = acc[im][jn][3] + b1e;
            if (relu) {
                o00 = fmaxf(o00, 0.f); o01 = fmaxf(o01, 0.f);
                o10 = fmaxf(o10, 0.f); o11 = fmaxf(o11, 0.f);
            }
            *(float2*)(C + (size_t)r * N + c)       = make_float2(o00, o01);
            *(float2*)(C + (size_t)(r + 8) * N + c) = make_float2(o10, o11);
        }
    }
}

// ---------------- fused weight transposes (ONE launch) ----------------
#define WT_TOTAL (25600 + 25600 + 196608 + 196608 + 25600)
__global__ void wtrans_all(const float* __restrict__ Wg_in, const float* __restrict__ Wv_in,
                           const float* __restrict__ Wg_h,  const float* __restrict__ Wv_h,
                           const float* __restrict__ Wg_out,
                           float* __restrict__ Wgt_in, float* __restrict__ Wvt_in,
                           float* __restrict__ Wgt_h,  float* __restrict__ Wvt_h,
                           float* __restrict__ Wgt_out)
{
    for (int i = blockIdx.x * blockDim.x + threadIdx.x; i < WT_TOTAL;
         i += gridDim.x * blockDim.x) {
        int j = i;
        if (j < 25600) {                       // Wg_in (101x256, skip row 0) -> [256][100]
            int n = j / 100, k = j % 100;
            Wgt_in[j] = Wg_in[(size_t)(k + 1) * WH + n];
        } else if ((j -= 25600) < 25600) {     // Wv_in
            int n = j / 100, k = j % 100;
            Wvt_in[j] = Wv_in[(size_t)(k + 1) * WH + n];
        } else if ((j -= 25600) < 196608) {    // Wg_h (3 x 256x256)
            int l = j / 65536, r = j % 65536;
            int n = r / 256, k = r % 256;
            Wgt_h[j] = Wg_h[(size_t)l * 65536 + (size_t)k * WH + n];
        } else if ((j -= 196608) < 196608) {   // Wv_h
            int l = j / 65536, r = j % 65536;
            int n = r / 256, k = r % 256;
            Wvt_h[j] = Wv_h[(size_t)l * 65536 + (size_t)k * WH + n];
        } else {                                // Wg_out (256x100) -> [100][256]
            j -= 196608;
            int n = j / 256, k = j % 256;
            Wgt_out[j] = Wg_out[(size_t)k * DIMN + n];
        }
    }
}

// ---------------- fused GEMV + error: vNew = H·w + b0; err += residual^2 ------
__global__ __launch_bounds__(256) void gemv_err(
    const float* __restrict__ H, const float* __restrict__ w,
    const float* __restrict__ b,
    const float* __restrict__ vOld, const float* __restrict__ stoch,
    const float* __restrict__ tg, int i,
    float* __restrict__ vNew, float* __restrict__ err, int doErr)
{
    __shared__ __align__(16) float ws[WH];
    ws[threadIdx.x] = w[threadIdx.x];
    __syncthreads();
    int warp = threadIdx.x >> 5, lane = threadIdx.x & 31;
    int row = blockIdx.x * 8 + warp;
    const float4* hr = (const float4*)(H + (size_t)row * WH);
    const float4* wr = (const float4*)ws;
    float acc = 0.f;
#pragma unroll
    for (int q = 0; q < 2; ++q) {
        float4 h4 = hr[q * 32 + lane];
        float4 w4 = wr[q * 32 + lane];
        acc += h4.x * w4.x + h4.y * w4.y + h4.z * w4.z + h4.w * w4.w;
    }
#pragma unroll
    for (int o = 16; o; o >>= 1) acc += __shfl_xor_sync(0xffffffffu, acc, o);
    if (lane == 0) {
        float v = acc + b[0];
        vNew[row] = v;
        if (doErr) {
            float h = tg[i + 1] - tg[i];
            float e = v - vOld[row] * (1.f + RRATE * h) - stoch[row];
            err[row] += e * e;
        }
    }
}

// ---------------- step: vol, stoch_int, S update ----------------
__global__ __launch_bounds__(256) void step_kernel(
    const float* __restrict__ S_old, const float* __restrict__ vp,
    const float* __restrict__ grad, const float* __restrict__ tg, int i,
    float* __restrict__ S_new, float* __restrict__ stoch)
{
    int warp = threadIdx.x >> 5, lane = threadIdx.x & 31;
    int b = blockIdx.x * 8 + warp;
    float h  = tg[i + 1] - tg[i];
    float sq = sqrtf(h);
    float rh = RRATE * h;
    const float* Sr = S_old + (size_t)b * DIMN;
    const float* vr = vp   + (size_t)b * DIMN;
    const float* gr = grad + (size_t)b * DIMN;
    float acc = 0.f;
    for (int d = lane; d < DIMN; d += 32) {
        float s   = Sr[d];
        float vol = s * (vr[d] * sq);
        acc += gr[d] * vol;
        S_new[(size_t)b * DIMN + d] = s + rh * s + vol;
    }
#pragma unroll
    for (int o = 16; o; o >>= 1) acc += __shfl_xor_sync(0xffffffffu, acc, o);
    if (lane == 0) stoch[b] = acc;
}

// ---------------- output packing: [v_f | S_f | error] ----------------
__global__ void pack_kernel(const float* __restrict__ v, const float* __restrict__ S,
                            const float* __restrict__ err, float* __restrict__ out)
{
    int i = blockIdx.x * 256 + threadIdx.x;
    if (i < BSZ * DIMN) out[BSZ + i] = S[i];
    if (i < BSZ) {
        out[i] = v[i];
        out[BSZ + BSZ * DIMN + i] = err[i];
    }
}

// ---------------- host-side helpers ----------------
static void gemm(const float* A, const float* Wt, const float* bias, const float* w0,
                 const float* tg, int tIdx, float* C, int M, int N, int K, int relu)
{
    dim3 grid((N + 63) / 64, M / 128);
    gemm_mma<<<grid, 256, DYN_SMEM>>>(A, Wt, Wt, bias, bias, w0, w0, tg, tIdx,
                                      C, N, K, relu, 1 << 30, 0);
}

struct DualW {
    const float *Wgt_in, *Wvt_in, *Wgt_h, *Wvt_h;
    const float *bg_in, *bv_in, *bg_h, *bv_h;
    const float *Wg_in, *Wv_in;   // originals (row 0 = t weights)
};

// dual trunk: both MLPs (g rows 0..8191, v rows 8192..16383); result in hB
static void dual_trunk(const float* S, const float* tg, int tIdx, const DualW& W,
                       float* hA, float* hB)
{
    dim3 grid(WH / 64, 128);   // (4, 128) = 512 CTAs
    gemm_mma<<<grid, 256, DYN_SMEM>>>(S, W.Wgt_in, W.Wvt_in, W.bg_in, W.bv_in,
                                      W.Wg_in, W.Wv_in, tg, tIdx,
                                      hA, WH, DIMN, 1, 64, 1);
    gemm_mma<<<grid, 256, DYN_SMEM>>>(hA, W.Wgt_h, W.Wvt_h, W.bg_h, W.bv_h,
                                      nullptr, nullptr, nullptr, 0,
                                      hB, WH, WH, 1, 64, 0);
    gemm_mma<<<grid, 256, DYN_SMEM>>>(hB, W.Wgt_h + 65536, W.Wvt_h + 65536,
                                      W.bg_h + WH, W.bv_h + WH,
                                      nullptr, nullptr, nullptr, 0,
                                      hA, WH, WH, 1, 64, 0);
    gemm_mma<<<grid, 256, DYN_SMEM>>>(hA, W.Wgt_h + 2 * 65536, W.Wvt_h + 2 * 65536,
                                      W.bg_h + 2 * WH, W.bv_h + 2 * WH,
                                      nullptr, nullptr, nullptr, 0,
                                      hB, WH, WH, 1, 64, 0);
}

extern "C" void kernel_launch(void* const* d_in, const int* in_sizes, int n_in,
                              void* d_out, int out_size)
{
    const float* S0     = (const float*)d_in[0];
    const float* dW     = (const float*)d_in[1];
    const float* tg     = (const float*)d_in[2];
    const float* Vm     = (const float*)d_in[3];
    const float* Wg_in  = (const float*)d_in[4];
    const float* bg_in  = (const float*)d_in[5];
    const float* Wg_h   = (const float*)d_in[6];
    const float* bg_h   = (const float*)d_in[7];
    const float* Wg_out = (const float*)d_in[8];
    const float* bg_out = (const float*)d_in[9];
    const float* Wv_in  = (const float*)d_in[10];
    const float* bv_in  = (const float*)d_in[11];
    const float* Wv_h   = (const float*)d_in[12];
    const float* bv_h   = (const float*)d_in[13];
    const float* Wv_out = (const float*)d_in[14];
    const float* bv_out = (const float*)d_in[15];

    float *volpre, *Sb, *hd, *grad, *vb, *stoch, *err;
    float *Wgt_in, *Wgt_h, *Wgt_out, *Wvt_in, *Wvt_h;
    cudaGetSymbolAddress((void**)&volpre, g_volpre);
    cudaGetSymbolAddress((void**)&Sb,     g_Sbuf);
    cudaGetSymbolAddress((void**)&hd,     g_hdual);
    cudaGetSymbolAddress((void**)&grad,   g_grad);
    cudaGetSymbolAddress((void**)&vb,     g_vbuf);
    cudaGetSymbolAddress((void**)&stoch,  g_stoch);
    cudaGetSymbolAddress((void**)&err,    g_err);
    cudaGetSymbolAddress((void**)&Wgt_in, g_Wgt_in);
    cudaGetSymbolAddress((void**)&Wgt_h,  g_Wgt_h);
    cudaGetSymbolAddress((void**)&Wgt_out,g_Wgt_out);
    cudaGetSymbolAddress((void**)&Wvt_in, g_Wvt_in);
    cudaGetSymbolAddress((void**)&Wvt_h,  g_Wvt_h);

    float* Sbuf0 = Sb;
    float* Sbuf1 = Sb + (size_t)BSZ * DIMN;
    float* hA = hd;
    float* hB = hd + (size_t)2 * BSZ * WH;
    float* vA = vb;
    float* vBp = vb + BSZ;

    DualW W{Wgt_in, Wvt_in, Wgt_h, Wvt_h, bg_in, bv_in, bg_h, bv_h, Wg_in, Wv_in};

    // launch 0: weight transposes
    wtrans_all<<<512, 256>>>(Wg_in, Wv_in, Wg_h, Wv_h, Wg_out,
                             Wgt_in, Wvt_in, Wgt_h, Wvt_h, Wgt_out);

    // launch 1: volpre = dW @ V^T (B operand is V itself, [N,K] K-major)
    gemm(dW, Vm, nullptr, nullptr, nullptr, 0, volpre, NSTEP * BSZ, DIMN, DIMN, 0);

    // launches 2-5: dual trunk on [t0, S0]  (ncu -s 5 -c 1 lands on a dual hidden GEMM)
    dual_trunk(S0, tg, 0, W, hA, hB);
    gemm(hB, Wgt_out, bg_out, nullptr, nullptr, 0, grad, BSZ, DIMN, WH, 0); // grad_0
    gemv_err<<<BSZ / 8, 256>>>(hB + (size_t)BSZ * WH, Wv_out, bv_out,
                               nullptr, nullptr, tg, 0, vA, err, 0);        // v_0

    cudaMemsetAsync(err, 0, BSZ * sizeof(float));

    const float* Scur = S0;
    float* vOld = vA;
    float* vNew = vBp;
    int sflip = 0;
    for (int i = 0; i < NSTEP; ++i) {
        float* Snew = sflip ? Sbuf1 : Sbuf0;
        // vol / stoch_int / S_new (uses grad_i = grad(t_i, S_i))
        step_kernel<<<BSZ / 8, 256>>>(Scur, volpre + (size_t)i * BSZ * DIMN,
                                      grad, tg, i, Snew, stoch);
        // both MLPs on [t_{i+1}, S_{i+1}] in one stacked trunk
        dual_trunk(Snew, tg, i + 1, W, hA, hB);
        gemm(hB, Wgt_out, bg_out, nullptr, nullptr, 0, grad, BSZ, DIMN, WH, 0); // grad_{i+1}
        gemv_err<<<BSZ / 8, 256>>>(hB + (size_t)BSZ * WH, Wv_out, bv_out,
                                   vOld, stoch, tg, i, vNew, err, 1);           // v_{i+1} + err
        Scur = Snew; sflip ^= 1;
        float* t = vOld; vOld = vNew; vNew = t;
    }

    // output: [v_f (8192) | S_f (8192*100) | error (8192)]
    pack_kernel<<<(BSZ * DIMN) / 256, 256>>>(vOld, Scur, err, (float*)d_out);
}

// round 7
// speedup vs baseline: 1.1479x; 1.0395x over previous
#include <cuda_runtime.h>
#include <cuda_fp16.h>
#include <cstdint>
#include <cstddef>

#define BSZ   8192
#define DIMN  100
#define NSTEP 49
#define WH    256
#define RRATE 0.05f

// ---------------- device scratch (static, no allocations) ----------------
__device__ float g_volpre[(size_t)NSTEP * BSZ * DIMN]; // 160.6 MB
__device__ float g_Sbuf[2][BSZ * DIMN];
__device__ float g_hdual[2][(size_t)2 * BSZ * WH];     // dual-MLP activations [16384][256]
__device__ float g_grad[BSZ * DIMN];
__device__ float g_vbuf[2][BSZ];
__device__ float g_stoch[BSZ];
__device__ float g_err[BSZ];
// transposed weights: Wt[n*K + k] = W[k*N + n]
__device__ float g_Wgt_in[WH * DIMN];
__device__ float g_Wgt_h[3][WH * WH];
__device__ float g_Wgt_out[DIMN * WH];
__device__ float g_Wvt_in[WH * DIMN];
__device__ float g_Wvt_h[3][WH * WH];

// ---------------- helpers ----------------
__device__ __forceinline__ uint32_t smem_u32(const void* p) {
    uint32_t a;
    asm("{ .reg .u64 t; cvta.to.shared.u64 t, %1; cvt.u32.u64 %0, t; }" : "=r"(a) : "l"(p));
    return a;
}
__device__ __forceinline__ void split2(float x0, float x1, uint32_t& h, uint32_t& l) {
    __half2 hh = __floats2half2_rn(x0, x1);
    float2 hf = __half22float2(hh);
    __half2 ll = __floats2half2_rn(x0 - hf.x, x1 - hf.y);
    h = *reinterpret_cast<uint32_t*>(&hh);
    l = *reinterpret_cast<uint32_t*>(&ll);
}
__device__ __forceinline__ void mma16(float d[4], const uint32_t a[4],
                                      uint32_t b0, uint32_t b1) {
    asm volatile(
        "mma.sync.aligned.m16n8k16.row.col.f32.f16.f16.f32 "
        "{%0,%1,%2,%3}, {%4,%5,%6,%7}, {%8,%9}, {%0,%1,%2,%3};"
        : "+f"(d[0]), "+f"(d[1]), "+f"(d[2]), "+f"(d[3])
        : "r"(a[0]), "r"(a[1]), "r"(a[2]), "r"(a[3]), "r"(b0), "r"(b1));
}
__device__ __forceinline__ void ldm4(uint32_t r[4], uint32_t addr) {
    asm volatile("ldmatrix.sync.aligned.m8n8.x4.shared.b16 {%0,%1,%2,%3}, [%4];"
                 : "=r"(r[0]), "=r"(r[1]), "=r"(r[2]), "=r"(r[3]) : "r"(addr));
}

// smem layout per buffer (bytes): rows of 16 halves, row stride 48B (conflict-free)
//   Ah @ 0      (128 rows x 48B = 6144)
//   Al @ 6144
//   Bh @ 12288  (128 rows x 48B = 6144)
//   Bl @ 18432
#define A_LO_OFF  6144
#define B_HI_OFF  12288
#define B_LO_OFF  18432
#define BUF_BYTES 24576
#define DYN_SMEM  (2 * BUF_BYTES)        // 49152 = default dyn-smem limit

// ========== mma.sync fp16 (3x-split) GEMM, dual-weight, CTA 128x128 ==========
// C[M,N] = act( A @ Wt^T + bias + t*w0 );  BK=16, 256 thr (8 warps, warp 32x64),
// 2 CTAs/SM. blocks with blockIdx.y >= halfBlocks use the *1 weight set.
__global__ __launch_bounds__(256, 2)
void gemm_mma(const float* __restrict__ A,
              const float* __restrict__ Wt0, const float* __restrict__ Wt1,
              const float* __restrict__ bias0, const float* __restrict__ bias1,
              const float* __restrict__ w00, const float* __restrict__ w01,
              const float* __restrict__ tg, int tIdx,
              float* __restrict__ C, int N, int K, int relu,
              int halfBlocks, int wrapA)
{
    extern __shared__ uint32_t smw[];
    char* smc = (char*)smw;
    const uint32_t smemBase = smem_u32(smw);

    const int tid    = threadIdx.x;
    const int lane   = tid & 31;
    const int wid    = tid >> 5;
    const int warp_m = wid & 3;        // 4 warps down M  -> 32 rows each
    const int warp_n = wid >> 2;       // 2 warps along N -> 64 cols each
    const int mBase  = blockIdx.y * 128;
    const int nBase  = blockIdx.x * 128;
    const bool hiH   = (int)blockIdx.y >= halfBlocks;
    const float* Wt   = hiH ? Wt1   : Wt0;
    const float* bias = hiH ? bias1 : bias0;
    const float* w0   = hiH ? w01   : w00;

    const int qrow = lane >> 2;        // 0..7
    const int qk   = lane & 3;         // 0..3

    float acc[2][8][4];
#pragma unroll
    for (int i = 0; i < 2; ++i)
#pragma unroll
        for (int j = 0; j < 8; ++j)
#pragma unroll
            for (int q = 0; q < 4; ++q) acc[i][j][q] = 0.f;

    // global-load indices (A rows r0/r1, B rows r0/r1; both tiles are 128 rows)
    const int r0  = tid >> 2;                  // 0..63
    const int r1  = r0 + 64;
    const int c40 = (tid & 3) << 2;            // k offset 0,4,8,12
    int ar0 = mBase + r0, ar1 = mBase + r1;
    if (wrapA) { ar0 &= (BSZ - 1); ar1 &= (BSZ - 1); }
    const int gn0 = nBase + r0, gn1 = nBase + r1;

    // ldmatrix source offsets (bytes, relative to buffer base)
    const int l15 = lane & 15;
    const int lc  = (lane >> 4) << 4;          // 0 or 16
    const uint32_t offA0 = (uint32_t)(warp_m * 32 + l15) * 48 + lc;
    const uint32_t offA1 = offA0 + 16 * 48;
    const uint32_t offB  = (uint32_t)B_HI_OFF + (uint32_t)(warp_n * 64 + l15) * 48 + lc;

    const int nChunks = (K + 15) >> 4;

    float4 av0, av1, bv0, bv1;
    auto prefetch = [&](int kc) {
        const int gc = (kc << 4) + c40;
        av0 = av1 = bv0 = bv1 = make_float4(0.f, 0.f, 0.f, 0.f);
        if (gc < K) {
            av0 = *(const float4*)(A + (size_t)ar0 * K + gc);
            av1 = *(const float4*)(A + (size_t)ar1 * K + gc);
            if (gn0 < N) bv0 = *(const float4*)(Wt + (size_t)gn0 * K + gc);
            if (gn1 < N) bv1 = *(const float4*)(Wt + (size_t)gn1 * K + gc);
        }
    };
    auto store = [&](int b) {
        char* buf = smc + b * BUF_BYTES;
        const uint32_t rowOff0 = (uint32_t)r0 * 48 + c40 * 2;
        const uint32_t rowOff1 = (uint32_t)r1 * 48 + c40 * 2;
        uint32_t h0, l0, h1, l1;
        split2(av0.x, av0.y, h0, l0); split2(av0.z, av0.w, h1, l1);
        *(uint2*)(buf + rowOff0)            = make_uint2(h0, h1);
        *(uint2*)(buf + A_LO_OFF + rowOff0) = make_uint2(l0, l1);
        split2(av1.x, av1.y, h0, l0); split2(av1.z, av1.w, h1, l1);
        *(uint2*)(buf + rowOff1)            = make_uint2(h0, h1);
        *(uint2*)(buf + A_LO_OFF + rowOff1) = make_uint2(l0, l1);
        split2(bv0.x, bv0.y, h0, l0); split2(bv0.z, bv0.w, h1, l1);
        *(uint2*)(buf + B_HI_OFF + rowOff0) = make_uint2(h0, h1);
        *(uint2*)(buf + B_LO_OFF + rowOff0) = make_uint2(l0, l1);
        split2(bv1.x, bv1.y, h0, l0); split2(bv1.z, bv1.w, h1, l1);
        *(uint2*)(buf + B_HI_OFF + rowOff1) = make_uint2(h0, h1);
        *(uint2*)(buf + B_LO_OFF + rowOff1) = make_uint2(l0, l1);
    };

    prefetch(0);
    store(0);

    for (int kc = 0; kc < nChunks; ++kc) {
        __syncthreads();
        const bool more = (kc + 1 < nChunks);
        if (more) prefetch(kc + 1);

        const uint32_t base = smemBase + (kc & 1) * BUF_BYTES;

        uint32_t ax0[4], ax1[4], bb[4][4];
        // ---- pass 1: Ah * Bh (bh fragments stay resident) ----
        ldm4(ax0, base + offA0);
        ldm4(ax1, base + offA1);
#pragma unroll
        for (int t = 0; t < 4; ++t) ldm4(bb[t], base + offB + t * (16 * 48));
#pragma unroll
        for (int t = 0; t < 4; ++t) {
            mma16(acc[0][2 * t],     ax0, bb[t][0], bb[t][2]);
            mma16(acc[1][2 * t],     ax1, bb[t][0], bb[t][2]);
            mma16(acc[0][2 * t + 1], ax0, bb[t][1], bb[t][3]);
            mma16(acc[1][2 * t + 1], ax1, bb[t][1], bb[t][3]);
        }
        // ---- pass 2: Al * Bh (reuse resident bh; al overwrites a regs) ----
        {
            uint32_t al0[4], al1[4];
            ldm4(al0, base + offA0 + A_LO_OFF);
            ldm4(al1, base + offA1 + A_LO_OFF);
#pragma unroll
            for (int t = 0; t < 4; ++t) {
                mma16(acc[0][2 * t],     al0, bb[t][0], bb[t][2]);
                mma16(acc[1][2 * t],     al1, bb[t][0], bb[t][2]);
                mma16(acc[0][2 * t + 1], al0, bb[t][1], bb[t][3]);
                mma16(acc[1][2 * t + 1], al1, bb[t][1], bb[t][3]);
            }
        }
        // ---- pass 3: Ah * Bl (bl reuses bh registers) ----
#pragma unroll
        for (int t = 0; t < 4; ++t) ldm4(bb[t], base + offB + (B_LO_OFF - B_HI_OFF) + t * (16 * 48));
#pragma unroll
        for (int t = 0; t < 4; ++t) {
            mma16(acc[0][2 * t],     ax0, bb[t][0], bb[t][2]);
            mma16(acc[1][2 * t],     ax1, bb[t][0], bb[t][2]);
            mma16(acc[0][2 * t + 1], ax0, bb[t][1], bb[t][3]);
            mma16(acc[1][2 * t + 1], ax1, bb[t][1], bb[t][3]);
        }

        if (more) store((kc + 1) & 1);
    }

    // ---------------- epilogue ----------------
    const float tval = w0 ? __ldg(tg + tIdx) : 0.f;
#pragma unroll
    for (int jn = 0; jn < 8; ++jn) {
        int c = nBase + warp_n * 64 + jn * 8 + 2 * qk;
        if (c >= N) continue;
        float b0e = 0.f, b1e = 0.f;
        if (bias) { b0e = __ldg(bias + c); b1e = __ldg(bias + c + 1); }
        if (w0)   { b0e += tval * __ldg(w0 + c); b1e += tval * __ldg(w0 + c + 1); }
#pragma unroll
        for (int im = 0; im < 2; ++im) {
            int r = mBase + warp_m * 32 + im * 16 + qrow;
            float o00 = acc[im][jn][0] + b0e, o01 = acc[im][jn][1] + b1e;
            float o10 = acc[im][jn][2] + b0e, o11 = acc[im][jn][3] + b1e;
            if (relu) {
                o00 = fmaxf(o00, 0.f); o01 = fmaxf(o01, 0.f);
                o10 = fmaxf(o10, 0.f); o11 = fmaxf(o11, 0.f);
            }
            *(float2*)(C + (size_t)r * N + c)       = make_float2(o00, o01);
            *(float2*)(C + (size_t)(r + 8) * N + c) = make_float2(o10, o11);
        }
    }
}

// ---------------- fused weight transposes (ONE launch) ----------------
#define WT_TOTAL (25600 + 25600 + 196608 + 196608 + 25600)
__global__ void wtrans_all(const float* __restrict__ Wg_in, const float* __restrict__ Wv_in,
                           const float* __restrict__ Wg_h,  const float* __restrict__ Wv_h,
                           const float* __restrict__ Wg_out,
                           float* __restrict__ Wgt_in, float* __restrict__ Wvt_in,
                           float* __restrict__ Wgt_h,  float* __restrict__ Wvt_h,
                           float* __restrict__ Wgt_out)
{
    for (int i = blockIdx.x * blockDim.x + threadIdx.x; i < WT_TOTAL;
         i += gridDim.x * blockDim.x) {
        int j = i;
        if (j < 25600) {                       // Wg_in (101x256, skip row 0) -> [256][100]
            int n = j / 100, k = j % 100;
            Wgt_in[j] = Wg_in[(size_t)(k + 1) * WH + n];
        } else if ((j -= 25600) < 25600) {     // Wv_in
            int n = j / 100, k = j % 100;
            Wvt_in[j] = Wv_in[(size_t)(k + 1) * WH + n];
        } else if ((j -= 25600) < 196608) {    // Wg_h (3 x 256x256)
            int l = j / 65536, r = j % 65536;
            int n = r / 256, k = r % 256;
            Wgt_h[j] = Wg_h[(size_t)l * 65536 + (size_t)k * WH + n];
        } else if ((j -= 196608) < 196608) {   // Wv_h
            int l = j / 65536, r = j % 65536;
            int n = r / 256, k = r % 256;
            Wvt_h[j] = Wv_h[(size_t)l * 65536 + (size_t)k * WH + n];
        } else {                                // Wg_out (256x100) -> [100][256]
            j -= 196608;
            int n = j / 256, k = j % 256;
            Wgt_out[j] = Wg_out[(size_t)k * DIMN + n];
        }
    }
}

// ---------------- fused GEMV + error: vNew = H·w + b0; err += residual^2 ------
__global__ __launch_bounds__(256) void gemv_err(
    const float* __restrict__ H, const float* __restrict__ w,
    const float* __restrict__ b,
    const float* __restrict__ vOld, const float* __restrict__ stoch,
    const float* __restrict__ tg, int i,
    float* __restrict__ vNew, float* __restrict__ err, int doErr)
{
    __shared__ __align__(16) float ws[WH];
    ws[threadIdx.x] = w[threadIdx.x];
    __syncthreads();
    int warp = threadIdx.x >> 5, lane = threadIdx.x & 31;
    int row = blockIdx.x * 8 + warp;
    const float4* hr = (const float4*)(H + (size_t)row * WH);
    const float4* wr = (const float4*)ws;
    float acc = 0.f;
#pragma unroll
    for (int q = 0; q < 2; ++q) {
        float4 h4 = hr[q * 32 + lane];
        float4 w4 = wr[q * 32 + lane];
        acc += h4.x * w4.x + h4.y * w4.y + h4.z * w4.z + h4.w * w4.w;
    }
#pragma unroll
    for (int o = 16; o; o >>= 1) acc += __shfl_xor_sync(0xffffffffu, acc, o);
    if (lane == 0) {
        float v = acc + b[0];
        vNew[row] = v;
        if (doErr) {
            float h = tg[i + 1] - tg[i];
            float e = v - vOld[row] * (1.f + RRATE * h) - stoch[row];
            err[row] += e * e;
        }
    }
}

// ---------------- step: vol, stoch_int, S update ----------------
__global__ __launch_bounds__(256) void step_kernel(
    const float* __restrict__ S_old, const float* __restrict__ vp,
    const float* __restrict__ grad, const float* __restrict__ tg, int i,
    float* __restrict__ S_new, float* __restrict__ stoch)
{
    int warp = threadIdx.x >> 5, lane = threadIdx.x & 31;
    int b = blockIdx.x * 8 + warp;
    float h  = tg[i + 1] - tg[i];
    float sq = sqrtf(h);
    float rh = RRATE * h;
    const float* Sr = S_old + (size_t)b * DIMN;
    const float* vr = vp   + (size_t)b * DIMN;
    const float* gr = grad + (size_t)b * DIMN;
    float acc = 0.f;
    for (int d = lane; d < DIMN; d += 32) {
        float s   = Sr[d];
        float vol = s * (vr[d] * sq);
        acc += gr[d] * vol;
        S_new[(size_t)b * DIMN + d] = s + rh * s + vol;
    }
#pragma unroll
    for (int o = 16; o; o >>= 1) acc += __shfl_xor_sync(0xffffffffu, acc, o);
    if (lane == 0) stoch[b] = acc;
}

// ---------------- output packing: [v_f | S_f | error] ----------------
__global__ void pack_kernel(const float* __restrict__ v, const float* __restrict__ S,
                            const float* __restrict__ err, float* __restrict__ out)
{
    int i = blockIdx.x * 256 + threadIdx.x;
    if (i < BSZ * DIMN) out[BSZ + i] = S[i];
    if (i < BSZ) {
        out[i] = v[i];
        out[BSZ + BSZ * DIMN + i] = err[i];
    }
}

// ---------------- host-side helpers ----------------
static void gemm(const float* A, const float* Wt, const float* bias, const float* w0,
                 const float* tg, int tIdx, float* C, int M, int N, int K, int relu)
{
    dim3 grid((N + 127) / 128, M / 128);
    gemm_mma<<<grid, 256, DYN_SMEM>>>(A, Wt, Wt, bias, bias, w0, w0, tg, tIdx,
                                      C, N, K, relu, 1 << 30, 0);
}

struct DualW {
    const float *Wgt_in, *Wvt_in, *Wgt_h, *Wvt_h;
    const float *bg_in, *bv_in, *bg_h, *bv_h;
    const float *Wg_in, *Wv_in;   // originals (row 0 = t weights)
};

// dual trunk: both MLPs (g rows 0..8191, v rows 8192..16383); result in hB
static void dual_trunk(const float* S, const float* tg, int tIdx, const DualW& W,
                       float* hA, float* hB)
{
    dim3 grid(WH / 128, 128);   // (2, 128) = 256 CTAs
    gemm_mma<<<grid, 256, DYN_SMEM>>>(S, W.Wgt_in, W.Wvt_in, W.bg_in, W.bv_in,
                                      W.Wg_in, W.Wv_in, tg, tIdx,
                                      hA, WH, DIMN, 1, 64, 1);
    gemm_mma<<<grid, 256, DYN_SMEM>>>(hA, W.Wgt_h, W.Wvt_h, W.bg_h, W.bv_h,
                                      nullptr, nullptr, nullptr, 0,
                                      hB, WH, WH, 1, 64, 0);
    gemm_mma<<<grid, 256, DYN_SMEM>>>(hB, W.Wgt_h + 65536, W.Wvt_h + 65536,
                                      W.bg_h + WH, W.bv_h + WH,
                                      nullptr, nullptr, nullptr, 0,
                                      hA, WH, WH, 1, 64, 0);
    gemm_mma<<<grid, 256, DYN_SMEM>>>(hA, W.Wgt_h + 2 * 65536, W.Wvt_h + 2 * 65536,
                                      W.bg_h + 2 * WH, W.bv_h + 2 * WH,
                                      nullptr, nullptr, nullptr, 0,
                                      hB, WH, WH, 1, 64, 0);
}

extern "C" void kernel_launch(void* const* d_in, const int* in_sizes, int n_in,
                              void* d_out, int out_size)
{
    const float* S0     = (const float*)d_in[0];
    const float* dW     = (const float*)d_in[1];
    const float* tg     = (const float*)d_in[2];
    const float* Vm     = (const float*)d_in[3];
    const float* Wg_in  = (const float*)d_in[4];
    const float* bg_in  = (const float*)d_in[5];
    const float* Wg_h   = (const float*)d_in[6];
    const float* bg_h   = (const float*)d_in[7];
    const float* Wg_out = (const float*)d_in[8];
    const float* bg_out = (const float*)d_in[9];
    const float* Wv_in  = (const float*)d_in[10];
    const float* bv_in  = (const float*)d_in[11];
    const float* Wv_h   = (const float*)d_in[12];
    const float* bv_h   = (const float*)d_in[13];
    const float* Wv_out = (const float*)d_in[14];
    const float* bv_out = (const float*)d_in[15];

    float *volpre, *Sb, *hd, *grad, *vb, *stoch, *err;
    float *Wgt_in, *Wgt_h, *Wgt_out, *Wvt_in, *Wvt_h;
    cudaGetSymbolAddress((void**)&volpre, g_volpre);
    cudaGetSymbolAddress((void**)&Sb,     g_Sbuf);
    cudaGetSymbolAddress((void**)&hd,     g_hdual);
    cudaGetSymbolAddress((void**)&grad,   g_grad);
    cudaGetSymbolAddress((void**)&vb,     g_vbuf);
    cudaGetSymbolAddress((void**)&stoch,  g_stoch);
    cudaGetSymbolAddress((void**)&err,    g_err);
    cudaGetSymbolAddress((void**)&Wgt_in, g_Wgt_in);
    cudaGetSymbolAddress((void**)&Wgt_h,  g_Wgt_h);
    cudaGetSymbolAddress((void**)&Wgt_out,g_Wgt_out);
    cudaGetSymbolAddress((void**)&Wvt_in, g_Wvt_in);
    cudaGetSymbolAddress((void**)&Wvt_h,  g_Wvt_h);

    float* Sbuf0 = Sb;
    float* Sbuf1 = Sb + (size_t)BSZ * DIMN;
    float* hA = hd;
    float* hB = hd + (size_t)2 * BSZ * WH;
    float* vA = vb;
    float* vBp = vb + BSZ;

    DualW W{Wgt_in, Wvt_in, Wgt_h, Wvt_h, bg_in, bv_in, bg_h, bv_h, Wg_in, Wv_in};

    // launch 0: weight transposes
    wtrans_all<<<512, 256>>>(Wg_in, Wv_in, Wg_h, Wv_h, Wg_out,
                             Wgt_in, Wvt_in, Wgt_h, Wvt_h, Wgt_out);

    // launch 1: volpre = dW @ V^T (B operand is V itself, [N,K] K-major)
    gemm(dW, Vm, nullptr, nullptr, nullptr, 0, volpre, NSTEP * BSZ, DIMN, DIMN, 0);

    // launches 2-5: dual trunk on [t0, S0]  (ncu -s 5 -c 1 lands on a dual hidden GEMM)
    dual_trunk(S0, tg, 0, W, hA, hB);
    gemm(hB, Wgt_out, bg_out, nullptr, nullptr, 0, grad, BSZ, DIMN, WH, 0); // grad_0
    gemv_err<<<BSZ / 8, 256>>>(hB + (size_t)BSZ * WH, Wv_out, bv_out,
                               nullptr, nullptr, tg, 0, vA, err, 0);        // v_0

    cudaMemsetAsync(err, 0, BSZ * sizeof(float));

    const float* Scur = S0;
    float* vOld = vA;
    float* vNew = vBp;
    int sflip = 0;
    for (int i = 0; i < NSTEP; ++i) {
        float* Snew = sflip ? Sbuf1 : Sbuf0;
        // vol / stoch_int / S_new (uses grad_i = grad(t_i, S_i))
        step_kernel<<<BSZ / 8, 256>>>(Scur, volpre + (size_t)i * BSZ * DIMN,
                                      grad, tg, i, Snew, stoch);
        // both MLPs on [t_{i+1}, S_{i+1}] in one stacked trunk
        dual_trunk(Snew, tg, i + 1, W, hA, hB);
        gemm(hB, Wgt_out, bg_out, nullptr, nullptr, 0, grad, BSZ, DIMN, WH, 0); // grad_{i+1}
        gemv_err<<<BSZ / 8, 256>>>(hB + (size_t)BSZ * WH, Wv_out, bv_out,
                                   vOld, stoch, tg, i, vNew, err, 1);           // v_{i+1} + err
        Scur = Snew; sflip ^= 1;
        float* t = vOld; vOld = vNew; vNew = t;
    }

    // output: [v_f (8192) | S_f (8192*100) | error (8192)]
    pack_kernel<<<(BSZ * DIMN) / 256, 256>>>(vOld, Scur, err, (float*)d_out);
}